// round 6
// baseline (speedup 1.0000x reference)
#include <cuda_runtime.h>
#include <cuda_bf16.h>

#define NN 20000
#define NF 64
#define NT 10
#define TN 10
#define KN 15
#define KLOC 16
#define NE 320000
#define NB_RED 160
#define NODES_PER_RED 125

typedef unsigned long long u64;

// packed f32x2 FMA: one issue slot, two FMAs (ptxas never auto-emits this)
__device__ __forceinline__ u64 ffma2(u64 a, u64 b, u64 c) {
    u64 d;
    asm("fma.rn.f32x2 %0, %1, %2, %3;" : "=l"(d) : "l"(a), "l"(b), "l"(c));
    return d;
}
__device__ __forceinline__ float2 unpack2(u64 v) {
    float2 r;
    asm("mov.b64 {%0, %1}, %2;" : "=f"(r.x), "=f"(r.y) : "l"(v));
    return r;
}

// ---------------- device scratch (no allocations allowed) ----------------
__device__ int   g_deg[NN];
__device__ int   g_start[NN];
__device__ int   g_cur[NN];
__device__ int   g_cnt[NN];
__device__ int   g_ebuf[NE];
__device__ int   g_dbuf[NE];
__device__ int   g_neigh[NN * KN];
__device__ int   g_dmin[NN];
__device__ float g_partS[NB_RED];
__device__ float g_partX[NB_RED * NF];
__device__ float g_hC2[NT * TN];
__device__ float g_hy2[NT * TN];
__device__ float g_consts[8];  // 0: -1/eps, 1: 1-alpha, 2: 2*alpha, 3: alpha

// ---------------- phase 0: neighbor construction ----------------
__global__ void k_zero() {
    int i = blockIdx.x * blockDim.x + threadIdx.x;
    if (i < NN) { g_deg[i] = 0; g_cur[i] = 0; g_cnt[i] = 0; }
}

__global__ void k_deg(const int* __restrict__ ei) {
    int e = blockIdx.x * blockDim.x + threadIdx.x;
    if (e < NE) atomicAdd(&g_deg[ei[e]], 1);
}

// exclusive prefix sum of g_deg -> g_start (1 block, warp-shuffle based)
__global__ void k_scan() {
    __shared__ int wsum[32];
    __shared__ int woff[32];
    __shared__ int s_carry, s_total;
    int t = threadIdx.x, lane = t & 31, w = t >> 5;
    if (t == 0) s_carry = 0;
    __syncthreads();
    for (int base = 0; base < NN; base += 1024) {
        int i = base + t;
        int v = (i < NN) ? g_deg[i] : 0;
        int incl = v;
        #pragma unroll
        for (int off = 1; off < 32; off <<= 1) {
            int o = __shfl_up_sync(0xffffffffu, incl, off);
            if (lane >= off) incl += o;
        }
        if (lane == 31) wsum[w] = incl;
        __syncthreads();
        if (w == 0) {
            int sv = wsum[lane];
            int inc2 = sv;
            #pragma unroll
            for (int off = 1; off < 32; off <<= 1) {
                int o = __shfl_up_sync(0xffffffffu, inc2, off);
                if (lane >= off) inc2 += o;
            }
            woff[lane] = inc2 - sv;
            if (lane == 31) s_total = inc2;
        }
        __syncthreads();
        if (i < NN) g_start[i] = s_carry + woff[w] + incl - v;
        __syncthreads();
        if (t == 0) s_carry += s_total;
        __syncthreads();
    }
}

__global__ void k_scatter(const int* __restrict__ ei) {
    int e = blockIdx.x * blockDim.x + threadIdx.x;
    if (e >= NE) return;
    int s = ei[e];
    int pos = g_start[s] + atomicAdd(&g_cur[s], 1);
    g_ebuf[pos] = e;
    g_dbuf[pos] = ei[NE + e];
}

// per node: pick dsts of the min(deg,15) smallest edge ids in increasing
// order == first edges in original order (matches stable argsort + rank drop).
__global__ void k_select() {
    int n = blockIdx.x * blockDim.x + threadIdx.x;
    if (n >= NN) return;
    int d = g_deg[n], s0 = g_start[n];
    int dmv = d < KN ? d : KN;
    g_dmin[n] = dmv;
    int last = -1;
    for (int s = 0; s < KN; s++) {
        int selid = 0;
        if (s < dmv) {
            int best = 0x7fffffff, bd = 0;
            for (int i = 0; i < d; i++) {
                int e = g_ebuf[s0 + i];
                if (e > last && e < best) { best = e; bd = g_dbuf[s0 + i]; }
            }
            last = best;
            selid = bd;
        }
        g_neigh[n * KN + s] = selid;
        atomicAdd(&g_cnt[selid], 1);
    }
}

// ---------------- phase 0b: eps = 0.05*mean(M)+1e-6 (closed form) ----------------
__global__ void k_part(const float* __restrict__ x) {
    __shared__ float sred[256];
    __shared__ float sx[4 * 64];
    int b = blockIdx.x, t = threadIdx.x;
    int lo = b * NODES_PER_RED;
    float ps = 0.f;
    if (t < NODES_PER_RED) {
        int i = lo + t;
        float w = (float)(g_cnt[i] + 1);
        const float* xr = x + (size_t)i * NF;
        float s = 0.f;
        for (int f = 0; f < NF; f++) s += xr[f] * xr[f];
        ps = w * s;
    }
    sred[t] = ps;
    __syncthreads();
    for (int off = 128; off > 0; off >>= 1) {
        if (t < off) sred[t] += sred[t + off];
        __syncthreads();
    }
    if (t == 0) g_partS[b] = sred[0];

    int f = t & 63, g = t >> 6;
    float pv = 0.f;
    for (int i = lo + g; i < lo + NODES_PER_RED; i += 4) {
        float w = (float)(g_cnt[i] + 1);
        pv += w * x[(size_t)i * NF + f];
    }
    sx[g * 64 + f] = pv;
    __syncthreads();
    if (t < 64) g_partX[b * 64 + t] = sx[t] + sx[64 + t] + sx[128 + t] + sx[192 + t];
}

__global__ void k_final(const float* __restrict__ tf, const float* __restrict__ tpl,
                        const float* __restrict__ alpha0) {
    __shared__ float sS[256];
    __shared__ float sSx[64];
    __shared__ float sSt[64];
    __shared__ float sHy[100];
    int t = threadIdx.x;
    float v = (t < NB_RED) ? g_partS[t] : 0.f;
    sS[t] = v;
    __syncthreads();
    for (int off = 128; off > 0; off >>= 1) {
        if (t < off) sS[t] += sS[t + off];
        __syncthreads();
    }
    if (t < 64) {
        float s = 0.f;
        for (int b = 0; b < NB_RED; b++) s += g_partX[b * 64 + t];
        sSx[t] = s;
        float s2 = 0.f;
        for (int r = 0; r < 100; r++) s2 += tf[r * 64 + t];
        sSt[t] = s2;
    }
    if (t < 100) {
        const float* r = tf + t * 64;
        float ss = 0.f;
        for (int f = 0; f < 64; f++) ss += r[f] * r[f];
        sHy[t] = ss;
        g_hy2[t] = ss;
        int tt = t / 10, m = t % 10;
        float hc = 0.f;
        for (int rr = 0; rr < 10; rr++) {
            float c = tpl[tt * 100 + m * 10 + rr];
            hc += c * c;
        }
        g_hC2[t] = hc * 0.1f;
    }
    __syncthreads();
    if (t == 0) {
        float Ssq = sS[0];
        float Stsq = 0.f;
        for (int r = 0; r < 100; r++) Stsq += sHy[r];
        const float invKN = 1.f / (16.f * (float)NN);
        float dot = 0.f;
        for (int f = 0; f < 64; f++) dot += (sSx[f] * invKN) * (sSt[f] * 0.01f);
        float meanM = Ssq * invKN + Stsq * 0.01f - 2.f * dot;
        float eps = 0.05f * meanM + 1e-6f;
        float a = 1.f / (1.f + __expf(-alpha0[0]));
        g_consts[0] = -1.f / eps;
        g_consts[1] = 1.f - a;
        g_consts[2] = 2.f * a;
        g_consts[3] = a;
    }
}

// ---------------- main kernel: 1 block/node, 1 warp/template ----------------
// lane: k = lane&15 (local-graph row), h = lane>>4 (column half), 5 cols/lane.
// Identities: colsum(Tp) == q == 0.1 exactly after each v-update; star graph
// collapses the GW tensor product to row-0 dots. Montgomery batch inversion
// turns the 5 per-iteration v-divisions into one MUFU.RCP.
__global__ __launch_bounds__(320, 2) void k_main(
    const float* __restrict__ x, const float* __restrict__ tpl,
    const float* __restrict__ tf, float* __restrict__ out) {
    __shared__ __align__(16) float s_x[16][68];
    __shared__ float s_C2[10 * 10 * 12];
    __shared__ float s_hx2[16];
    __shared__ float s_red[256];
    __shared__ int s_dm;

    int n = blockIdx.x;
    int tid = threadIdx.x;
    if (tid == 0) s_dm = g_dmin[n];

    if (tid < 256) {
        int row = tid >> 4, f4 = tid & 15;
        int src = (row == 0) ? n : g_neigh[n * KN + row - 1];
        float4 v = *(const float4*)(x + (size_t)src * NF + f4 * 4);
        *(float4*)&s_x[row][f4 * 4] = v;
    }
    for (int idx = tid; idx < 1000; idx += 320) {
        int tt = idx / 100, rem = idx % 100, r = rem / 10, mm = rem % 10;
        s_C2[tt * 120 + r * 12 + mm] = tpl[idx];
    }
    __syncthreads();
    if (tid < 256) {
        int row = tid >> 4, seg = tid & 15;
        float p = 0.f;
        #pragma unroll
        for (int j = 0; j < 4; j++) {
            float v = s_x[row][seg * 4 + j];
            p += v * v;
        }
        s_red[tid] = p;
    }
    __syncthreads();
    if (tid < 16) {
        float s = 0.f;
        for (int seg = 0; seg < 16; seg++) s += s_red[tid * 16 + seg];
        s_hx2[tid] = s;
    }
    __syncthreads();

    const int lane = tid & 31, t = tid >> 5;
    const int k = lane & 15, h = lane >> 4;
    const int dm = s_dm;
    const float negieps = g_consts[0], c1 = g_consts[1], c2 = g_consts[2],
                alpha = g_consts[3];

    const int rb = t * 10 + 5 * h;
    const float* c2base = &s_C2[t * 120 + 5 * h * 12];

    // hoisted row-sums of C2 for the lane's 5 template rows
    float rs[5];
    #pragma unroll
    for (int j = 0; j < 5; j++) {
        const float* cr = c2base + j * 12;
        float4 ca = *(const float4*)cr;
        float4 cb = *(const float4*)(cr + 4);
        float2 cc = *(const float2*)(cr + 8);
        rs[j] = ca.x + ca.y + ca.z + ca.w + cb.x + cb.y + cb.z + cb.w +
                cc.x + cc.y;
    }

    // ---- M[k][5h+j] via packed f32x2 FMA: 160 FFMA2 instead of 320 FFMA ----
    u64 acc2[5] = {0ull, 0ull, 0ull, 0ull, 0ull};
    const ulonglong2* tf2 = (const ulonglong2*)tf;  // L1/L2-resident 25.6KB
    const ulonglong2* xr2 = (const ulonglong2*)&s_x[k][0];
    #pragma unroll 4
    for (int f4 = 0; f4 < 16; f4++) {
        ulonglong2 xv = xr2[f4];
        #pragma unroll
        for (int j = 0; j < 5; j++) {
            ulonglong2 c = tf2[(rb + j) * 16 + f4];
            acc2[j] = ffma2(xv.x, c.x, acc2[j]);
            acc2[j] = ffma2(xv.y, c.y, acc2[j]);
        }
    }

    const float inv1p = __fdividef(1.f, (float)(1 + dm));
    const float pk = (k <= dm) ? inv1p : 0.f;
    const float maskk = (k >= 1 && k <= dm) ? 1.f : 0.f;
    const float hC1k = (k == 0) ? (float)dm * inv1p : maskk * inv1p;

    float Mreg[5], cst[5];  // cst = hC1k + hC2 (merged structure constant)
    #pragma unroll
    for (int j = 0; j < 5; j++) {
        float2 p2 = unpack2(acc2[j]);
        cst[j] = hC1k + g_hC2[rb + j];
        Mreg[j] = s_hx2[k] + g_hy2[rb + j] - 2.f * (p2.x + p2.y);
    }

    float Tpreg[5], vv[5], Kreg[5], sel[5];
    float u = 0.f;
    #pragma unroll
    for (int j = 0; j < 5; j++) {
        Tpreg[j] = pk * 0.1f;  // independent coupling init
        vv[j] = 1.f;           // g = 0
    }

    for (int o = 0; o < 4; o++) {
        // gather row 0 of Tp for all 10 columns (colsum == 0.1 by identity)
        float T0f[10];
        {
            float t0[5], t0o[5];
            #pragma unroll
            for (int j = 0; j < 5; j++)
                t0[j] = __shfl_sync(0xffffffffu, Tpreg[j], h << 4);
            #pragma unroll
            for (int j = 0; j < 5; j++)
                t0o[j] = __shfl_xor_sync(0xffffffffu, t0[j], 16);
            #pragma unroll
            for (int j = 0; j < 5; j++) {
                if (h == 0) { T0f[j] = t0[j];  T0f[5 + j] = t0o[j]; }
                else        { T0f[j] = t0o[j]; T0f[5 + j] = t0[j]; }
            }
        }
        // b_r = Tp[0] . C2[t][r][:]; a_r = 0.1*rowsum(C2 r) - b_r
        #pragma unroll
        for (int j = 0; j < 5; j++) {
            const float* cr = c2base + j * 12;
            float4 ca = *(const float4*)cr;
            float4 cb = *(const float4*)(cr + 4);
            float2 cc = *(const float2*)(cr + 8);
            float b_ = T0f[0] * ca.x + T0f[1] * ca.y + T0f[2] * ca.z +
                       T0f[3] * ca.w + T0f[4] * cb.x + T0f[5] * cb.y +
                       T0f[6] * cb.z + T0f[7] * cb.w + T0f[8] * cc.x +
                       T0f[9] * cc.y;
            sel[j] = (k == 0) ? (0.1f * rs[j] - b_) : maskk * b_;
        }
        if (o == 3) break;

        #pragma unroll
        for (int j = 0; j < 5; j++) {
            float G = c1 * Mreg[j] + c2 * (cst[j] - 2.f * sel[j]);
            Kreg[j] = __expf(G * negieps);
        }
        #pragma unroll
        for (int it = 0; it < 5; it++) {
            float s = Kreg[0] * vv[0] + Kreg[1] * vv[1] + Kreg[2] * vv[2] +
                      Kreg[3] * vv[3] + Kreg[4] * vv[4];
            s += __shfl_xor_sync(0xffffffffu, s, 16);  // row sum over 10 cols
            u = __fdividef(pk, s);
            // 5 column sums over 16 rows (butterflies, independent chains)
            float w[5];
            #pragma unroll
            for (int j = 0; j < 5; j++) {
                float ww = Kreg[j] * u;
                ww += __shfl_xor_sync(0xffffffffu, ww, 1);
                ww += __shfl_xor_sync(0xffffffffu, ww, 2);
                ww += __shfl_xor_sync(0xffffffffu, ww, 4);
                ww += __shfl_xor_sync(0xffffffffu, ww, 8);
                w[j] = ww;
            }
            // Montgomery batch inverse: vv[j] = 0.1 / w[j], one RCP total
            float p1 = w[0] * w[1];
            float p2 = p1 * w[2];
            float p3 = p2 * w[3];
            float p4 = p3 * w[4];
            float r = __fdividef(0.1f, p4);   // 0.1 * rcp(prod)
            vv[4] = r * p3;
            float r3 = r * w[4];
            vv[3] = r3 * p2;
            float r2 = r3 * w[3];
            vv[2] = r2 * p1;
            float r1 = r2 * w[2];
            vv[1] = r1 * w[0];
            vv[0] = r1 * w[1];
        }
        #pragma unroll
        for (int j = 0; j < 5; j++) Tpreg[j] = Kreg[j] * u * vv[j];
    }

    float S1 = 0.f, S2 = 0.f, Sab = 0.f;
    #pragma unroll
    for (int j = 0; j < 5; j++) {
        S1 += Mreg[j] * Tpreg[j];
        S2 += cst[j] * Tpreg[j];
        Sab += sel[j] * Tpreg[j];
    }
    float d = c1 * S1 + alpha * (S2 - 2.f * Sab);
    d += __shfl_xor_sync(0xffffffffu, d, 1);
    d += __shfl_xor_sync(0xffffffffu, d, 2);
    d += __shfl_xor_sync(0xffffffffu, d, 4);
    d += __shfl_xor_sync(0xffffffffu, d, 8);
    d += __shfl_xor_sync(0xffffffffu, d, 16);
    if (lane == 0) out[n * NT + t] = d;
}

extern "C" void kernel_launch(void* const* d_in, const int* in_sizes, int n_in,
                              void* d_out, int out_size) {
    const float* x = (const float*)d_in[0];
    const int* ei = (const int*)d_in[1];
    const float* tpl = (const float*)d_in[2];
    const float* tf = (const float*)d_in[3];
    const float* alpha0 = (const float*)d_in[4];
    float* out = (float*)d_out;

    k_zero<<<(NN + 255) / 256, 256>>>();
    k_deg<<<(NE + 255) / 256, 256>>>(ei);
    k_scan<<<1, 1024>>>();
    k_scatter<<<(NE + 255) / 256, 256>>>(ei);
    k_select<<<(NN + 255) / 256, 256>>>();
    k_part<<<NB_RED, 256>>>(x);
    k_final<<<1, 256>>>(tf, tpl, alpha0);
    k_main<<<NN, 320>>>(x, tpl, tf, out);
}

// round 7
// speedup vs baseline: 1.1116x; 1.1116x over previous
#include <cuda_runtime.h>
#include <cuda_bf16.h>

#define NN 20000
#define NF 64
#define NT 10
#define TN 10
#define KN 15
#define KLOC 16
#define NE 320000
#define NB_RED 160
#define NODES_PER_RED 125

typedef unsigned long long u64;

// packed f32x2 FMA: one issue slot, two FMAs (ptxas never auto-emits this)
__device__ __forceinline__ u64 ffma2(u64 a, u64 b, u64 c) {
    u64 d;
    asm("fma.rn.f32x2 %0, %1, %2, %3;" : "=l"(d) : "l"(a), "l"(b), "l"(c));
    return d;
}
__device__ __forceinline__ float2 unpack2(u64 v) {
    float2 r;
    asm("mov.b64 {%0, %1}, %2;" : "=f"(r.x), "=f"(r.y) : "l"(v));
    return r;
}

// ---------------- device scratch (no allocations allowed) ----------------
__device__ int   g_deg[NN];
__device__ int   g_start[NN];
__device__ int   g_cur[NN];
__device__ int   g_cnt[NN];
__device__ int   g_ebuf[NE];
__device__ int   g_dbuf[NE];
__device__ int   g_neigh[NN * KN];
__device__ int   g_dmin[NN];
__device__ float g_partS[NB_RED];
__device__ float g_partX[NB_RED * NF];
__device__ float g_hC2[NT * TN];
__device__ float g_hy2[NT * TN];
__device__ float g_consts[8];  // 0: -1/eps, 1: 1-alpha, 2: 2*alpha, 3: alpha

// ---------------- phase 0: neighbor construction ----------------
__global__ void k_zero() {
    int i = blockIdx.x * blockDim.x + threadIdx.x;
    if (i < NN) { g_deg[i] = 0; g_cur[i] = 0; g_cnt[i] = 0; }
}

__global__ void k_deg(const int* __restrict__ ei) {
    int e = blockIdx.x * blockDim.x + threadIdx.x;
    if (e < NE) atomicAdd(&g_deg[ei[e]], 1);
}

// exclusive prefix sum of g_deg -> g_start (1 block, warp-shuffle based)
__global__ void k_scan() {
    __shared__ int wsum[32];
    __shared__ int woff[32];
    __shared__ int s_carry, s_total;
    int t = threadIdx.x, lane = t & 31, w = t >> 5;
    if (t == 0) s_carry = 0;
    __syncthreads();
    for (int base = 0; base < NN; base += 1024) {
        int i = base + t;
        int v = (i < NN) ? g_deg[i] : 0;
        int incl = v;
        #pragma unroll
        for (int off = 1; off < 32; off <<= 1) {
            int o = __shfl_up_sync(0xffffffffu, incl, off);
            if (lane >= off) incl += o;
        }
        if (lane == 31) wsum[w] = incl;
        __syncthreads();
        if (w == 0) {
            int sv = wsum[lane];
            int inc2 = sv;
            #pragma unroll
            for (int off = 1; off < 32; off <<= 1) {
                int o = __shfl_up_sync(0xffffffffu, inc2, off);
                if (lane >= off) inc2 += o;
            }
            woff[lane] = inc2 - sv;
            if (lane == 31) s_total = inc2;
        }
        __syncthreads();
        if (i < NN) g_start[i] = s_carry + woff[w] + incl - v;
        __syncthreads();
        if (t == 0) s_carry += s_total;
        __syncthreads();
    }
}

__global__ void k_scatter(const int* __restrict__ ei) {
    int e = blockIdx.x * blockDim.x + threadIdx.x;
    if (e >= NE) return;
    int s = ei[e];
    int pos = g_start[s] + atomicAdd(&g_cur[s], 1);
    g_ebuf[pos] = e;
    g_dbuf[pos] = ei[NE + e];
}

// per node: pick dsts of the min(deg,15) smallest edge ids in increasing
// order == first edges in original order (matches stable argsort + rank drop).
__global__ void k_select() {
    int n = blockIdx.x * blockDim.x + threadIdx.x;
    if (n >= NN) return;
    int d = g_deg[n], s0 = g_start[n];
    int dmv = d < KN ? d : KN;
    g_dmin[n] = dmv;
    int last = -1;
    for (int s = 0; s < KN; s++) {
        int selid = 0;
        if (s < dmv) {
            int best = 0x7fffffff, bd = 0;
            for (int i = 0; i < d; i++) {
                int e = g_ebuf[s0 + i];
                if (e > last && e < best) { best = e; bd = g_dbuf[s0 + i]; }
            }
            last = best;
            selid = bd;
        }
        g_neigh[n * KN + s] = selid;
        atomicAdd(&g_cnt[selid], 1);
    }
}

// ---------------- phase 0b: eps = 0.05*mean(M)+1e-6 (closed form) ----------------
__global__ void k_part(const float* __restrict__ x) {
    __shared__ float sred[256];
    __shared__ float sx[4 * 64];
    int b = blockIdx.x, t = threadIdx.x;
    int lo = b * NODES_PER_RED;
    float ps = 0.f;
    if (t < NODES_PER_RED) {
        int i = lo + t;
        float w = (float)(g_cnt[i] + 1);
        const float* xr = x + (size_t)i * NF;
        float s = 0.f;
        for (int f = 0; f < NF; f++) s += xr[f] * xr[f];
        ps = w * s;
    }
    sred[t] = ps;
    __syncthreads();
    for (int off = 128; off > 0; off >>= 1) {
        if (t < off) sred[t] += sred[t + off];
        __syncthreads();
    }
    if (t == 0) g_partS[b] = sred[0];

    int f = t & 63, g = t >> 6;
    float pv = 0.f;
    for (int i = lo + g; i < lo + NODES_PER_RED; i += 4) {
        float w = (float)(g_cnt[i] + 1);
        pv += w * x[(size_t)i * NF + f];
    }
    sx[g * 64 + f] = pv;
    __syncthreads();
    if (t < 64) g_partX[b * 64 + t] = sx[t] + sx[64 + t] + sx[128 + t] + sx[192 + t];
}

__global__ void k_final(const float* __restrict__ tf, const float* __restrict__ tpl,
                        const float* __restrict__ alpha0) {
    __shared__ float sS[256];
    __shared__ float sSx[64];
    __shared__ float sSt[64];
    __shared__ float sHy[100];
    int t = threadIdx.x;
    float v = (t < NB_RED) ? g_partS[t] : 0.f;
    sS[t] = v;
    __syncthreads();
    for (int off = 128; off > 0; off >>= 1) {
        if (t < off) sS[t] += sS[t + off];
        __syncthreads();
    }
    if (t < 64) {
        float s = 0.f;
        for (int b = 0; b < NB_RED; b++) s += g_partX[b * 64 + t];
        sSx[t] = s;
        float s2 = 0.f;
        for (int r = 0; r < 100; r++) s2 += tf[r * 64 + t];
        sSt[t] = s2;
    }
    if (t < 100) {
        const float* r = tf + t * 64;
        float ss = 0.f;
        for (int f = 0; f < 64; f++) ss += r[f] * r[f];
        sHy[t] = ss;
        g_hy2[t] = ss;
        int tt = t / 10, m = t % 10;
        float hc = 0.f;
        for (int rr = 0; rr < 10; rr++) {
            float c = tpl[tt * 100 + m * 10 + rr];
            hc += c * c;
        }
        g_hC2[t] = hc * 0.1f;
    }
    __syncthreads();
    if (t == 0) {
        float Ssq = sS[0];
        float Stsq = 0.f;
        for (int r = 0; r < 100; r++) Stsq += sHy[r];
        const float invKN = 1.f / (16.f * (float)NN);
        float dot = 0.f;
        for (int f = 0; f < 64; f++) dot += (sSx[f] * invKN) * (sSt[f] * 0.01f);
        float meanM = Ssq * invKN + Stsq * 0.01f - 2.f * dot;
        float eps = 0.05f * meanM + 1e-6f;
        float a = 1.f / (1.f + __expf(-alpha0[0]));
        g_consts[0] = -1.f / eps;
        g_consts[1] = 1.f - a;
        g_consts[2] = 2.f * a;
        g_consts[3] = a;
    }
}

// ---------------- main kernel: 1 block = 2 nodes, 1 warp/template ----------------
// Warp t: lanes 0-15 = node A rows, lanes 16-31 = node B rows (same template t).
// Each lane owns the FULL 10-column row: row sums are in-register, u is
// per-lane; only column sums need cross-lane butterflies (within 16-lane
// groups). Two independent problems per warp double latency hiding.
// Identities: colsum(Tp) == q == 0.1 after each v-update; star graph collapses
// the GW tensor product to row-0 dots.
__global__ __launch_bounds__(320, 2) void k_main(
    const float* __restrict__ x, const float* __restrict__ tpl,
    const float* __restrict__ tf, float* __restrict__ out) {
    __shared__ __align__(16) float s_x[2][16][68];
    __shared__ float s_C2[10 * 10 * 12];   // rows padded to 12
    __shared__ float s_hx2[2][16];
    __shared__ float s_red[512];
    __shared__ int s_dm[2];

    int tid = threadIdx.x;
    int nA = blockIdx.x * 2;
    if (tid < 2) s_dm[tid] = g_dmin[nA + tid];

    // stage local-graph features for both nodes
    for (int idx = tid; idx < 512; idx += 320) {
        int gg = idx >> 8, row = (idx >> 4) & 15, f4 = idx & 15;
        int node = nA + gg;
        int src = (row == 0) ? node : g_neigh[node * KN + row - 1];
        float4 v = *(const float4*)(x + (size_t)src * NF + f4 * 4);
        *(float4*)&s_x[gg][row][f4 * 4] = v;
    }
    for (int idx = tid; idx < 1000; idx += 320) {
        int tt = idx / 100, rem = idx % 100, r = rem / 10, mm = rem % 10;
        s_C2[tt * 120 + r * 12 + mm] = tpl[idx];
    }
    __syncthreads();
    for (int idx = tid; idx < 512; idx += 320) {
        int gg = idx >> 8, row = (idx >> 4) & 15, seg = idx & 15;
        float p = 0.f;
        #pragma unroll
        for (int j = 0; j < 4; j++) {
            float v = s_x[gg][row][seg * 4 + j];
            p += v * v;
        }
        s_red[idx] = p;
    }
    __syncthreads();
    if (tid < 32) {
        int gg = tid >> 4, row = tid & 15;
        float s = 0.f;
        for (int seg = 0; seg < 16; seg++) s += s_red[gg * 256 + row * 16 + seg];
        s_hx2[gg][row] = s;
    }
    __syncthreads();

    const int lane = tid & 31, t = tid >> 5;
    const int g = lane >> 4, k = lane & 15;
    const int dm = s_dm[g];
    const float negieps = g_consts[0], c1 = g_consts[1], c2 = g_consts[2],
                alpha = g_consts[3];
    const int srclane = g << 4;           // lane holding row 0 of this group
    const float* c2base = &s_C2[t * 120];

    // ---- M[k][j] via packed f32x2 FMA (10 cols per lane) ----
    u64 acc2[10];
    #pragma unroll
    for (int j = 0; j < 10; j++) acc2[j] = 0ull;
    const ulonglong2* tf2 = (const ulonglong2*)tf;  // L1/L2-resident 25.6KB
    const ulonglong2* xr2 = (const ulonglong2*)&s_x[g][k][0];
    #pragma unroll 4
    for (int f4 = 0; f4 < 16; f4++) {
        ulonglong2 xv = xr2[f4];
        #pragma unroll
        for (int j = 0; j < 10; j++) {
            ulonglong2 c = tf2[(t * 10 + j) * 16 + f4];
            acc2[j] = ffma2(xv.x, c.x, acc2[j]);
            acc2[j] = ffma2(xv.y, c.y, acc2[j]);
        }
    }

    const float inv1p = __fdividef(1.f, (float)(1 + dm));
    const float pk = (k <= dm) ? inv1p : 0.f;
    const float maskk = (k >= 1 && k <= dm) ? 1.f : 0.f;
    const float hC1k = (k == 0) ? (float)dm * inv1p : maskk * inv1p;
    const float hx2 = s_hx2[g][k];

    float Mreg[10], cst[10];
    #pragma unroll
    for (int j = 0; j < 10; j++) {
        float2 p2 = unpack2(acc2[j]);
        cst[j] = hC1k + g_hC2[t * 10 + j];
        Mreg[j] = hx2 + g_hy2[t * 10 + j] - 2.f * (p2.x + p2.y);
    }

    float Tpreg[10], vv[10], Kreg[10], sel[10];
    float u = 0.f;
    #pragma unroll
    for (int j = 0; j < 10; j++) {
        Tpreg[j] = pk * 0.1f;  // independent coupling init
        vv[j] = 1.f;           // g = 0
    }

    for (int o = 0; o < 4; o++) {
        // gather row 0 of Tp for this group's problem (colsum == 0.1 identity)
        float T0f[10];
        #pragma unroll
        for (int j = 0; j < 10; j++)
            T0f[j] = __shfl_sync(0xffffffffu, Tpreg[j], srclane);
        // sel[r]: b_r = Tp0 . C2[t][r][:]; row-sum computed inline
        #pragma unroll
        for (int r = 0; r < 10; r++) {
            const float* cr = c2base + r * 12;
            float4 ca = *(const float4*)cr;
            float4 cb = *(const float4*)(cr + 4);
            float2 cc = *(const float2*)(cr + 8);
            float b_ = T0f[0] * ca.x + T0f[1] * ca.y + T0f[2] * ca.z +
                       T0f[3] * ca.w + T0f[4] * cb.x + T0f[5] * cb.y +
                       T0f[6] * cb.z + T0f[7] * cb.w + T0f[8] * cc.x +
                       T0f[9] * cc.y;
            float rsr = ca.x + ca.y + ca.z + ca.w + cb.x + cb.y + cb.z +
                        cb.w + cc.x + cc.y;
            sel[r] = (k == 0) ? (0.1f * rsr - b_) : maskk * b_;
        }
        if (o == 3) break;

        #pragma unroll
        for (int j = 0; j < 10; j++) {
            float G = c1 * Mreg[j] + c2 * (cst[j] - 2.f * sel[j]);
            Kreg[j] = __expf(G * negieps);
        }
        #pragma unroll
        for (int it = 0; it < 5; it++) {
            // row sum fully in-register; u per-lane
            float s = Kreg[0] * vv[0] + Kreg[1] * vv[1] + Kreg[2] * vv[2] +
                      Kreg[3] * vv[3] + Kreg[4] * vv[4] + Kreg[5] * vv[5] +
                      Kreg[6] * vv[6] + Kreg[7] * vv[7] + Kreg[8] * vv[8] +
                      Kreg[9] * vv[9];
            u = __fdividef(pk, s);
            // 10 column sums over 16 rows (independent butterfly chains)
            float w[10];
            #pragma unroll
            for (int j = 0; j < 10; j++) {
                float ww = Kreg[j] * u;
                ww += __shfl_xor_sync(0xffffffffu, ww, 1);
                ww += __shfl_xor_sync(0xffffffffu, ww, 2);
                ww += __shfl_xor_sync(0xffffffffu, ww, 4);
                ww += __shfl_xor_sync(0xffffffffu, ww, 8);
                w[j] = ww;
            }
            // two Montgomery 5-batches: vv[j] = 0.1 / w[j], 2 RCP total
            #pragma unroll
            for (int b = 0; b < 2; b++) {
                float* wb = w + b * 5;
                float* vb = vv + b * 5;
                float p1 = wb[0] * wb[1];
                float p2 = p1 * wb[2];
                float p3 = p2 * wb[3];
                float p4 = p3 * wb[4];
                float r = __fdividef(0.1f, p4);
                vb[4] = r * p3;
                float r3 = r * wb[4];
                vb[3] = r3 * p2;
                float r2 = r3 * wb[3];
                vb[2] = r2 * p1;
                float r1 = r2 * wb[2];
                vb[1] = r1 * wb[0];
                vb[0] = r1 * wb[1];
            }
        }
        #pragma unroll
        for (int j = 0; j < 10; j++) Tpreg[j] = Kreg[j] * u * vv[j];
    }

    float S1 = 0.f, S2 = 0.f, Sab = 0.f;
    #pragma unroll
    for (int j = 0; j < 10; j++) {
        S1 += Mreg[j] * Tpreg[j];
        S2 += cst[j] * Tpreg[j];
        Sab += sel[j] * Tpreg[j];
    }
    float d = c1 * S1 + alpha * (S2 - 2.f * Sab);
    d += __shfl_xor_sync(0xffffffffu, d, 1);
    d += __shfl_xor_sync(0xffffffffu, d, 2);
    d += __shfl_xor_sync(0xffffffffu, d, 4);
    d += __shfl_xor_sync(0xffffffffu, d, 8);
    if (k == 0) out[(nA + g) * NT + t] = d;
}

extern "C" void kernel_launch(void* const* d_in, const int* in_sizes, int n_in,
                              void* d_out, int out_size) {
    const float* x = (const float*)d_in[0];
    const int* ei = (const int*)d_in[1];
    const float* tpl = (const float*)d_in[2];
    const float* tf = (const float*)d_in[3];
    const float* alpha0 = (const float*)d_in[4];
    float* out = (float*)d_out;

    k_zero<<<(NN + 255) / 256, 256>>>();
    k_deg<<<(NE + 255) / 256, 256>>>(ei);
    k_scan<<<1, 1024>>>();
    k_scatter<<<(NE + 255) / 256, 256>>>(ei);
    k_select<<<(NN + 255) / 256, 256>>>();
    k_part<<<NB_RED, 256>>>(x);
    k_final<<<1, 256>>>(tf, tpl, alpha0);
    k_main<<<NN / 2, 320>>>(x, tpl, tf, out);
}

// round 8
// speedup vs baseline: 1.1454x; 1.0304x over previous
#include <cuda_runtime.h>
#include <cuda_bf16.h>

#define NN 20000
#define NF 64
#define NT 10
#define TN 10
#define KN 15
#define KLOC 16
#define NE 320000
#define NB_RED 160
#define NODES_PER_RED 125

typedef unsigned long long u64;

// packed f32x2 FMA: one issue slot, two FMAs (ptxas never auto-emits this)
__device__ __forceinline__ u64 ffma2(u64 a, u64 b, u64 c) {
    u64 d;
    asm("fma.rn.f32x2 %0, %1, %2, %3;" : "=l"(d) : "l"(a), "l"(b), "l"(c));
    return d;
}
__device__ __forceinline__ float2 unpack2(u64 v) {
    float2 r;
    asm("mov.b64 {%0, %1}, %2;" : "=f"(r.x), "=f"(r.y) : "l"(v));
    return r;
}

// ---------------- device scratch (no allocations allowed) ----------------
__device__ int   g_deg[NN];
__device__ int   g_start[NN];
__device__ int   g_cur[NN];
__device__ int   g_cnt[NN];
__device__ int   g_ebuf[NE];
__device__ int   g_dbuf[NE];
__device__ int   g_neigh[NN * KN];
__device__ int   g_dmin[NN];
__device__ float g_partS[NB_RED];
__device__ float g_partX[NB_RED * NF];
__device__ float g_hC2[NT * TN];
__device__ float g_hy2[NT * TN];
__device__ float g_consts[8];  // 0: -1/eps, 1: 1-alpha, 2: 2*alpha, 3: alpha

// ---------------- phase 0: neighbor construction ----------------
__global__ void k_zero() {
    int i = blockIdx.x * blockDim.x + threadIdx.x;
    if (i < NN) { g_deg[i] = 0; g_cur[i] = 0; g_cnt[i] = 0; }
}

__global__ void k_deg(const int* __restrict__ ei) {
    int e = blockIdx.x * blockDim.x + threadIdx.x;
    if (e < NE) atomicAdd(&g_deg[ei[e]], 1);
}

// exclusive prefix sum of g_deg -> g_start (1 block, warp-shuffle based)
__global__ void k_scan() {
    __shared__ int wsum[32];
    __shared__ int woff[32];
    __shared__ int s_carry, s_total;
    int t = threadIdx.x, lane = t & 31, w = t >> 5;
    if (t == 0) s_carry = 0;
    __syncthreads();
    for (int base = 0; base < NN; base += 1024) {
        int i = base + t;
        int v = (i < NN) ? g_deg[i] : 0;
        int incl = v;
        #pragma unroll
        for (int off = 1; off < 32; off <<= 1) {
            int o = __shfl_up_sync(0xffffffffu, incl, off);
            if (lane >= off) incl += o;
        }
        if (lane == 31) wsum[w] = incl;
        __syncthreads();
        if (w == 0) {
            int sv = wsum[lane];
            int inc2 = sv;
            #pragma unroll
            for (int off = 1; off < 32; off <<= 1) {
                int o = __shfl_up_sync(0xffffffffu, inc2, off);
                if (lane >= off) inc2 += o;
            }
            woff[lane] = inc2 - sv;
            if (lane == 31) s_total = inc2;
        }
        __syncthreads();
        if (i < NN) g_start[i] = s_carry + woff[w] + incl - v;
        __syncthreads();
        if (t == 0) s_carry += s_total;
        __syncthreads();
    }
}

__global__ void k_scatter(const int* __restrict__ ei) {
    int e = blockIdx.x * blockDim.x + threadIdx.x;
    if (e >= NE) return;
    int s = ei[e];
    int pos = g_start[s] + atomicAdd(&g_cur[s], 1);
    g_ebuf[pos] = e;
    g_dbuf[pos] = ei[NE + e];
}

// per node: pick dsts of the min(deg,15) smallest edge ids in increasing
// order == first edges in original order (matches stable argsort + rank drop).
__global__ void k_select() {
    int n = blockIdx.x * blockDim.x + threadIdx.x;
    if (n >= NN) return;
    int d = g_deg[n], s0 = g_start[n];
    int dmv = d < KN ? d : KN;
    g_dmin[n] = dmv;
    int last = -1;
    for (int s = 0; s < KN; s++) {
        int selid = 0;
        if (s < dmv) {
            int best = 0x7fffffff, bd = 0;
            for (int i = 0; i < d; i++) {
                int e = g_ebuf[s0 + i];
                if (e > last && e < best) { best = e; bd = g_dbuf[s0 + i]; }
            }
            last = best;
            selid = bd;
        }
        g_neigh[n * KN + s] = selid;
        atomicAdd(&g_cnt[selid], 1);
    }
}

// ---------------- phase 0b: eps = 0.05*mean(M)+1e-6 (closed form) ----------------
__global__ void k_part(const float* __restrict__ x) {
    __shared__ float sred[256];
    __shared__ float sx[4 * 64];
    int b = blockIdx.x, t = threadIdx.x;
    int lo = b * NODES_PER_RED;
    float ps = 0.f;
    if (t < NODES_PER_RED) {
        int i = lo + t;
        float w = (float)(g_cnt[i] + 1);
        const float* xr = x + (size_t)i * NF;
        float s = 0.f;
        for (int f = 0; f < NF; f++) s += xr[f] * xr[f];
        ps = w * s;
    }
    sred[t] = ps;
    __syncthreads();
    for (int off = 128; off > 0; off >>= 1) {
        if (t < off) sred[t] += sred[t + off];
        __syncthreads();
    }
    if (t == 0) g_partS[b] = sred[0];

    int f = t & 63, g = t >> 6;
    float pv = 0.f;
    for (int i = lo + g; i < lo + NODES_PER_RED; i += 4) {
        float w = (float)(g_cnt[i] + 1);
        pv += w * x[(size_t)i * NF + f];
    }
    sx[g * 64 + f] = pv;
    __syncthreads();
    if (t < 64) g_partX[b * 64 + t] = sx[t] + sx[64 + t] + sx[128 + t] + sx[192 + t];
}

__global__ void k_final(const float* __restrict__ tf, const float* __restrict__ tpl,
                        const float* __restrict__ alpha0) {
    __shared__ float sS[256];
    __shared__ float sSx[64];
    __shared__ float sSt[64];
    __shared__ float sHy[100];
    int t = threadIdx.x;
    float v = (t < NB_RED) ? g_partS[t] : 0.f;
    sS[t] = v;
    __syncthreads();
    for (int off = 128; off > 0; off >>= 1) {
        if (t < off) sS[t] += sS[t + off];
        __syncthreads();
    }
    if (t < 64) {
        float s = 0.f;
        for (int b = 0; b < NB_RED; b++) s += g_partX[b * 64 + t];
        sSx[t] = s;
        float s2 = 0.f;
        for (int r = 0; r < 100; r++) s2 += tf[r * 64 + t];
        sSt[t] = s2;
    }
    if (t < 100) {
        const float* r = tf + t * 64;
        float ss = 0.f;
        for (int f = 0; f < 64; f++) ss += r[f] * r[f];
        sHy[t] = ss;
        g_hy2[t] = ss;
        int tt = t / 10, m = t % 10;
        float hc = 0.f;
        for (int rr = 0; rr < 10; rr++) {
            float c = tpl[tt * 100 + m * 10 + rr];
            hc += c * c;
        }
        g_hC2[t] = hc * 0.1f;
    }
    __syncthreads();
    if (t == 0) {
        float Ssq = sS[0];
        float Stsq = 0.f;
        for (int r = 0; r < 100; r++) Stsq += sHy[r];
        const float invKN = 1.f / (16.f * (float)NN);
        float dot = 0.f;
        for (int f = 0; f < 64; f++) dot += (sSx[f] * invKN) * (sSt[f] * 0.01f);
        float meanM = Ssq * invKN + Stsq * 0.01f - 2.f * dot;
        float eps = 0.05f * meanM + 1e-6f;
        float a = 1.f / (1.f + __expf(-alpha0[0]));
        g_consts[0] = -1.f / eps;
        g_consts[1] = 1.f - a;
        g_consts[2] = 2.f * a;
        g_consts[3] = a;
    }
}

// ---------------- main kernel: 1 block = 2 nodes, 1 warp/template ----------------
// Warp t: lanes 0-15 = node A rows, lanes 16-31 = node B rows (same template).
// Each lane owns the FULL 10-column row. Register-pressure trick: the merged
// linearization constant GM = c1*M + c2*(hC1+hC2) lives in SMEM (padded
// stride 11 -> conflict-free), so the Sinkhorn loop keeps only ~55 live regs
// and the kernel fits 3 blocks/SM without spills.
// Identities: colsum(Tp) == q == 0.1 after each v-update; star graph collapses
// the GW tensor product to row-0 dots; G = GM - 2*c2*sel;
// dist = sum (GM - alpha*cst - c2*sel) * Tp.
__global__ __launch_bounds__(320, 3) void k_main(
    const float* __restrict__ x, const float* __restrict__ tpl,
    const float* __restrict__ tf, float* __restrict__ out) {
    __shared__ __align__(16) float s_x[2][16][68];
    __shared__ float s_C2[10 * 10 * 12];   // rows padded to 12
    __shared__ float s_GM[10][32][11];     // [warp][lane][j], stride 11
    __shared__ float s_hx2[2][16];
    __shared__ float s_red[512];
    __shared__ int s_dm[2];

    int tid = threadIdx.x;
    int nA = blockIdx.x * 2;
    if (tid < 2) s_dm[tid] = g_dmin[nA + tid];

    // stage local-graph features for both nodes
    for (int idx = tid; idx < 512; idx += 320) {
        int gg = idx >> 8, row = (idx >> 4) & 15, f4 = idx & 15;
        int node = nA + gg;
        int src = (row == 0) ? node : g_neigh[node * KN + row - 1];
        float4 v = *(const float4*)(x + (size_t)src * NF + f4 * 4);
        *(float4*)&s_x[gg][row][f4 * 4] = v;
    }
    for (int idx = tid; idx < 1000; idx += 320) {
        int tt = idx / 100, rem = idx % 100, r = rem / 10, mm = rem % 10;
        s_C2[tt * 120 + r * 12 + mm] = tpl[idx];
    }
    __syncthreads();
    for (int idx = tid; idx < 512; idx += 320) {
        int gg = idx >> 8, row = (idx >> 4) & 15, seg = idx & 15;
        float p = 0.f;
        #pragma unroll
        for (int j = 0; j < 4; j++) {
            float v = s_x[gg][row][seg * 4 + j];
            p += v * v;
        }
        s_red[idx] = p;
    }
    __syncthreads();
    if (tid < 32) {
        int gg = tid >> 4, row = tid & 15;
        float s = 0.f;
        for (int seg = 0; seg < 16; seg++) s += s_red[gg * 256 + row * 16 + seg];
        s_hx2[gg][row] = s;
    }
    __syncthreads();

    const int lane = tid & 31, t = tid >> 5;
    const int g = lane >> 4, k = lane & 15;
    const int dm = s_dm[g];
    const float negieps = g_consts[0], c1 = g_consts[1], c2 = g_consts[2],
                alpha = g_consts[3];
    const int srclane = g << 4;           // lane holding row 0 of this group
    const float* c2base = &s_C2[t * 120];
    float* gmrow = &s_GM[t][lane][0];

    const float inv1p = __fdividef(1.f, (float)(1 + dm));
    const float pk = (k <= dm) ? inv1p : 0.f;
    const float maskk = (k >= 1 && k <= dm) ? 1.f : 0.f;
    const float hC1k = (k == 0) ? (float)dm * inv1p : maskk * inv1p;
    const float hx2 = s_hx2[g][k];

    // ---- GM[j] = c1*M + c2*(hC1k + hC2), M via packed f32x2 FMA ----
    {
        u64 acc2[10];
        #pragma unroll
        for (int j = 0; j < 10; j++) acc2[j] = 0ull;
        const ulonglong2* tf2 = (const ulonglong2*)tf;
        const ulonglong2* xr2 = (const ulonglong2*)&s_x[g][k][0];
        #pragma unroll 4
        for (int f4 = 0; f4 < 16; f4++) {
            ulonglong2 xv = xr2[f4];
            #pragma unroll
            for (int j = 0; j < 10; j++) {
                ulonglong2 c = tf2[(t * 10 + j) * 16 + f4];
                acc2[j] = ffma2(xv.x, c.x, acc2[j]);
                acc2[j] = ffma2(xv.y, c.y, acc2[j]);
            }
        }
        #pragma unroll
        for (int j = 0; j < 10; j++) {
            float2 p2 = unpack2(acc2[j]);
            float M = hx2 + g_hy2[t * 10 + j] - 2.f * (p2.x + p2.y);
            float cst = hC1k + g_hC2[t * 10 + j];
            gmrow[j] = c1 * M + c2 * cst;
        }
    }

    float Tpreg[10], vv[10], Kreg[10], sel[10];
    float u = 0.f;
    #pragma unroll
    for (int j = 0; j < 10; j++) {
        Tpreg[j] = pk * 0.1f;  // independent coupling init
        vv[j] = 1.f;           // g = 0
    }

    for (int o = 0; o < 4; o++) {
        // gather row 0 of Tp for this group's problem (colsum == 0.1 identity)
        float T0f[10];
        #pragma unroll
        for (int j = 0; j < 10; j++)
            T0f[j] = __shfl_sync(0xffffffffu, Tpreg[j], srclane);
        // sel[r]: b_r = Tp0 . C2[t][r][:]; row-sum computed inline
        #pragma unroll
        for (int r = 0; r < 10; r++) {
            const float* cr = c2base + r * 12;
            float4 ca = *(const float4*)cr;
            float4 cb = *(const float4*)(cr + 4);
            float2 cc = *(const float2*)(cr + 8);
            float b_ = T0f[0] * ca.x + T0f[1] * ca.y + T0f[2] * ca.z +
                       T0f[3] * ca.w + T0f[4] * cb.x + T0f[5] * cb.y +
                       T0f[6] * cb.z + T0f[7] * cb.w + T0f[8] * cc.x +
                       T0f[9] * cc.y;
            float rsr = ca.x + ca.y + ca.z + ca.w + cb.x + cb.y + cb.z +
                        cb.w + cc.x + cc.y;
            sel[r] = (k == 0) ? (0.1f * rsr - b_) : maskk * b_;
        }
        if (o == 3) break;

        #pragma unroll
        for (int j = 0; j < 10; j++) {
            float G = gmrow[j] - 2.f * c2 * sel[j];
            Kreg[j] = __expf(G * negieps);
        }
        #pragma unroll
        for (int it = 0; it < 5; it++) {
            // row sum fully in-register; u per-lane
            float s = Kreg[0] * vv[0] + Kreg[1] * vv[1] + Kreg[2] * vv[2] +
                      Kreg[3] * vv[3] + Kreg[4] * vv[4] + Kreg[5] * vv[5] +
                      Kreg[6] * vv[6] + Kreg[7] * vv[7] + Kreg[8] * vv[8] +
                      Kreg[9] * vv[9];
            u = __fdividef(pk, s);
            // 10 column sums over 16 rows (independent butterfly chains)
            float w[10];
            #pragma unroll
            for (int j = 0; j < 10; j++) {
                float ww = Kreg[j] * u;
                ww += __shfl_xor_sync(0xffffffffu, ww, 1);
                ww += __shfl_xor_sync(0xffffffffu, ww, 2);
                ww += __shfl_xor_sync(0xffffffffu, ww, 4);
                ww += __shfl_xor_sync(0xffffffffu, ww, 8);
                w[j] = ww;
            }
            // two Montgomery 5-batches: vv[j] = 0.1 / w[j], 2 RCP total
            #pragma unroll
            for (int b = 0; b < 2; b++) {
                float* wb = w + b * 5;
                float* vb = vv + b * 5;
                float p1 = wb[0] * wb[1];
                float p2 = p1 * wb[2];
                float p3 = p2 * wb[3];
                float p4 = p3 * wb[4];
                float r = __fdividef(0.1f, p4);
                vb[4] = r * p3;
                float r3 = r * wb[4];
                vb[3] = r3 * p2;
                float r2 = r3 * wb[3];
                vb[2] = r2 * p1;
                float r1 = r2 * wb[2];
                vb[1] = r1 * wb[0];
                vb[0] = r1 * wb[1];
            }
        }
        #pragma unroll
        for (int j = 0; j < 10; j++) Tpreg[j] = Kreg[j] * u * vv[j];
    }

    // dist = sum_j (GM[j] - alpha*cst[j] - c2*sel[j]) * Tp[j]
    float d = 0.f;
    #pragma unroll
    for (int j = 0; j < 10; j++) {
        float cst = hC1k + g_hC2[t * 10 + j];
        d += (gmrow[j] - alpha * cst - c2 * sel[j]) * Tpreg[j];
    }
    d += __shfl_xor_sync(0xffffffffu, d, 1);
    d += __shfl_xor_sync(0xffffffffu, d, 2);
    d += __shfl_xor_sync(0xffffffffu, d, 4);
    d += __shfl_xor_sync(0xffffffffu, d, 8);
    if (k == 0) out[(nA + g) * NT + t] = d;
}

extern "C" void kernel_launch(void* const* d_in, const int* in_sizes, int n_in,
                              void* d_out, int out_size) {
    const float* x = (const float*)d_in[0];
    const int* ei = (const int*)d_in[1];
    const float* tpl = (const float*)d_in[2];
    const float* tf = (const float*)d_in[3];
    const float* alpha0 = (const float*)d_in[4];
    float* out = (float*)d_out;

    k_zero<<<(NN + 255) / 256, 256>>>();
    k_deg<<<(NE + 255) / 256, 256>>>(ei);
    k_scan<<<1, 1024>>>();
    k_scatter<<<(NE + 255) / 256, 256>>>(ei);
    k_select<<<(NN + 255) / 256, 256>>>();
    k_part<<<NB_RED, 256>>>(x);
    k_final<<<1, 256>>>(tf, tpl, alpha0);
    k_main<<<NN / 2, 320>>>(x, tpl, tf, out);
}